// round 1
// baseline (speedup 1.0000x reference)
#include <cuda_runtime.h>
#include <math.h>

#define NN 50000
#define NE 800000
#define HD 256
#define NG 64
#define SCAN_BLKS 196   // ceil(50000/256)

// ---------------- scratch (device globals; no runtime allocation) ----------------
__device__ __align__(16) float g_h [(size_t)NN*HD];   // GEMM output (also S1 [N,128] for attention)
__device__ __align__(16) float g_r [(size_t)NN*HD];   // post agg+relu
__device__ __align__(16) float g_xp[(size_t)NN*HD];   // layer activations
__device__ float g_dinv[NN];
__device__ int   g_cnt[NN];
__device__ int   g_incl[NN];
__device__ int   g_rowptr[NN+1];
__device__ int   g_cursor[NN];
__device__ int   g_col[NE];
__device__ int   g_bsum[SCAN_BLKS];
__device__ int   g_bscan[SCAN_BLKS];
__device__ __align__(16) float g_stat0[HD];
__device__ __align__(16) float g_stat1[HD];
__device__ __align__(16) float g_ain[HD], g_cin[HD];
__device__ __align__(16) float g_A[HD], g_C[HD];
__device__ __align__(16) float g_W0f[HD*HD];
__device__ __align__(16) float g_cb[HD];
__device__ float g_score[NN], g_w[NN];
__device__ float g_pm[SCAN_BLKS], g_ps[SCAN_BLKS];
__device__ float g_soft[2];
__device__ __align__(16) float g_pooled[NG*HD];
__device__ float g_cntf[NG];

// ---------------- init / zero ----------------
__global__ void zero_init() {
    int i = blockIdx.x * 256 + threadIdx.x;
    if (i < NN) g_cnt[i] = 0;
    if (i < NG*HD) g_pooled[i] = 0.f;
    if (i < NG) g_cntf[i] = 0.f;
    if (i < HD) { g_stat0[i] = 0.f; g_stat1[i] = 0.f; }
}

// ---------------- input BN stats (column sums over x) ----------------
__global__ void colstats_x(const float* __restrict__ x) {
    int t = threadIdx.x;  // column 0..255
    float s = 0.f, q = 0.f;
    for (int r = blockIdx.x; r < NN; r += gridDim.x) {
        float v = x[(size_t)r*HD + t];
        s += v; q += v*v;
    }
    atomicAdd(&g_stat0[t], s);
    atomicAdd(&g_stat1[t], q);
}

__global__ void finalize_in(const float* __restrict__ g, const float* __restrict__ b) {
    int t = threadIdx.x;
    float m = g_stat0[t] * (1.f/NN);
    float v = g_stat1[t] * (1.f/NN) - m*m;
    float rs = rsqrtf(v + 1e-5f);
    g_ain[t] = rs * g[t];
    g_cin[t] = b[t] - m * rs * g[t];
    g_stat0[t] = 0.f; g_stat1[t] = 0.f;
}

// Fold input-BN affine into W0: W0f[k][j] = a[k]*W0[k][j]; cb[j] = sum_k c[k]*W0[k][j]
__global__ void foldW0(const float* __restrict__ W0) {
    int k = blockIdx.x, j = threadIdx.x;
    g_W0f[k*HD + j] = g_ain[k] * W0[k*HD + j];
}
__global__ void foldB0(const float* __restrict__ W0) {
    int j = threadIdx.x;
    float s = 0.f;
    for (int k = 0; k < HD; k++) s += g_cin[k] * W0[k*HD + j];
    g_cb[j] = s;
}

// ---------------- degree / CSR build ----------------
__global__ void deg_kernel(const int* __restrict__ dst) {
    for (int e = blockIdx.x*blockDim.x + threadIdx.x; e < NE; e += gridDim.x*blockDim.x)
        atomicAdd(&g_cnt[dst[e]], 1);
}
__global__ void dinv_kernel() {
    int i = blockIdx.x*256 + threadIdx.x;
    if (i < NN) g_dinv[i] = rsqrtf((float)g_cnt[i] + 1.f);
}
__global__ void scan1() {
    __shared__ int sm[256];
    int t = threadIdx.x;
    int i = blockIdx.x*256 + t;
    int v = (i < NN) ? g_cnt[i] : 0;
    sm[t] = v; __syncthreads();
    for (int off = 1; off < 256; off <<= 1) {
        int tv = (t >= off) ? sm[t-off] : 0;
        __syncthreads();
        sm[t] += tv;
        __syncthreads();
    }
    if (i < NN) g_incl[i] = sm[t];
    if (t == 255) g_bsum[blockIdx.x] = sm[255];
}
__global__ void scan2() {
    __shared__ int sm[256];
    int t = threadIdx.x;
    sm[t] = (t < SCAN_BLKS) ? g_bsum[t] : 0; __syncthreads();
    for (int off = 1; off < 256; off <<= 1) {
        int tv = (t >= off) ? sm[t-off] : 0;
        __syncthreads();
        sm[t] += tv;
        __syncthreads();
    }
    if (t < SCAN_BLKS) g_bscan[t] = sm[t];
}
__global__ void scan3() {
    int t = threadIdx.x;
    int i = blockIdx.x*256 + t;
    if (i < NN) {
        int off = (blockIdx.x > 0) ? g_bscan[blockIdx.x-1] : 0;
        int ex = off + g_incl[i] - g_cnt[i];
        g_rowptr[i] = ex;
        g_cursor[i] = ex;
    }
    if (i == 0) g_rowptr[NN] = NE;
}
__global__ void fill_kernel(const int* __restrict__ src, const int* __restrict__ dst) {
    for (int e = blockIdx.x*blockDim.x + threadIdx.x; e < NE; e += gridDim.x*blockDim.x) {
        int d = dst[e];
        int p = atomicAdd(&g_cursor[d], 1);
        g_col[p] = src[e];
    }
}

// ---------------- SGEMM: C[M,Nn] = A[M,256] @ B[256,Nn] (+bias[Nn]) ----------------
__global__ __launch_bounds__(256, 2) void sgemm_kernel(
    const float* __restrict__ A, const float* __restrict__ B,
    const float* __restrict__ bias, float* __restrict__ C, int M, int Nn)
{
    const int K = 256;
    __shared__ float As[2][16][128];
    __shared__ float Bs[2][16][128];
    int tid = threadIdx.x;
    int bm = blockIdx.x * 128, bn = blockIdx.y * 128;
    int tx = tid & 15, ty = tid >> 4;

    int aRow = tid >> 1;         // 0..127
    int aC4  = (tid & 1) * 2;    // f4 col base within 16-wide K tile

    float4 ra[2], rb[2];

    auto LOADG = [&](int kt) {
        int k0 = kt * 16;
        #pragma unroll
        for (int i = 0; i < 2; i++) {
            int row = bm + aRow;
            if (row < M)
                ra[i] = *(const float4*)(A + (size_t)row*K + k0 + (aC4+i)*4);
            else
                ra[i] = make_float4(0.f,0.f,0.f,0.f);
        }
        #pragma unroll
        for (int i = 0; i < 2; i++) {
            int id = tid + 256*i;
            int k = id >> 5, n4 = id & 31;
            rb[i] = *(const float4*)(B + (size_t)(k0+k)*Nn + bn + n4*4);
        }
    };
    auto STORES = [&](int buf) {
        #pragma unroll
        for (int i = 0; i < 2; i++) {
            int kb = (aC4+i)*4;
            As[buf][kb+0][aRow] = ra[i].x;
            As[buf][kb+1][aRow] = ra[i].y;
            As[buf][kb+2][aRow] = ra[i].z;
            As[buf][kb+3][aRow] = ra[i].w;
        }
        #pragma unroll
        for (int i = 0; i < 2; i++) {
            int id = tid + 256*i;
            *(float4*)&Bs[buf][id>>5][(id&31)*4] = rb[i];
        }
    };

    float acc[8][8];
    #pragma unroll
    for (int i = 0; i < 8; i++)
        #pragma unroll
        for (int j = 0; j < 8; j++) acc[i][j] = 0.f;

    LOADG(0); STORES(0); __syncthreads();

    #pragma unroll
    for (int kt = 0; kt < 16; kt++) {
        int buf = kt & 1;
        if (kt < 15) LOADG(kt+1);
        #pragma unroll
        for (int k = 0; k < 16; k++) {
            float a_[8], b_[8];
            *(float4*)&a_[0] = *(const float4*)&As[buf][k][ty*8];
            *(float4*)&a_[4] = *(const float4*)&As[buf][k][ty*8+4];
            *(float4*)&b_[0] = *(const float4*)&Bs[buf][k][tx*8];
            *(float4*)&b_[4] = *(const float4*)&Bs[buf][k][tx*8+4];
            #pragma unroll
            for (int i = 0; i < 8; i++)
                #pragma unroll
                for (int j = 0; j < 8; j++)
                    acc[i][j] = fmaf(a_[i], b_[j], acc[i][j]);
        }
        if (kt < 15) { STORES(buf^1); __syncthreads(); }
    }

    float bv[8];
    #pragma unroll
    for (int j = 0; j < 8; j++) bv[j] = bias ? bias[bn + tx*8 + j] : 0.f;
    #pragma unroll
    for (int i = 0; i < 8; i++) {
        int row = bm + ty*8 + i;
        if (row < M) {
            float* cp = C + (size_t)row*Nn + bn + tx*8;
            float4 o0 = make_float4(acc[i][0]+bv[0], acc[i][1]+bv[1], acc[i][2]+bv[2], acc[i][3]+bv[3]);
            float4 o1 = make_float4(acc[i][4]+bv[4], acc[i][5]+bv[5], acc[i][6]+bv[6], acc[i][7]+bv[7]);
            *(float4*)cp = o0;
            *(float4*)(cp+4) = o1;
        }
    }
}

// ---------------- aggregation + bias + relu + BN-stat partials ----------------
// out = relu( sum_nb h[src]*dinv[src]*dinv[dst] + h[dst]*dinv^2 + b )
__global__ __launch_bounds__(128) void agg_kernel(const float* __restrict__ bias) {
    int t = threadIdx.x;         // column pair
    int c = t * 2;
    int row0 = blockIdx.x * 32;
    float psx=0.f, psy=0.f, pqx=0.f, pqy=0.f;
    for (int r = 0; r < 32; r++) {
        int i = row0 + r;
        if (i >= NN) break;
        float di = g_dinv[i];
        float2 hv = *(const float2*)(g_h + (size_t)i*HD + c);
        float ax = hv.x * di * di, ay = hv.y * di * di;
        int b0 = g_rowptr[i], e0 = g_rowptr[i+1];
        for (int p = b0; p < e0; p++) {
            int s = g_col[p];
            float cf = di * g_dinv[s];
            float2 hs = *(const float2*)(g_h + (size_t)s*HD + c);
            ax = fmaf(hs.x, cf, ax);
            ay = fmaf(hs.y, cf, ay);
        }
        float vx = fmaxf(ax + bias[c], 0.f);
        float vy = fmaxf(ay + bias[c+1], 0.f);
        *(float2*)(g_r + (size_t)i*HD + c) = make_float2(vx, vy);
        psx += vx; psy += vy; pqx += vx*vx; pqy += vy*vy;
    }
    atomicAdd(&g_stat0[c],   psx);
    atomicAdd(&g_stat0[c+1], psy);
    atomicAdd(&g_stat1[c],   pqx);
    atomicAdd(&g_stat1[c+1], pqy);
}

__global__ void finalize_hidden(const float* __restrict__ g, const float* __restrict__ b) {
    int t = threadIdx.x;
    float m = g_stat0[t] * (1.f/NN);
    float v = g_stat1[t] * (1.f/NN) - m*m;
    float rs = rsqrtf(v + 1e-5f);
    g_A[t] = rs * g[t];
    g_C[t] = b[t] - m * rs * g[t];
    g_stat0[t] = 0.f; g_stat1[t] = 0.f;
}

// xp = r*A + C (+ xp if residual)
__global__ void bnnorm_kernel(int residual) {
    int idx = blockIdx.x*256 + threadIdx.x;       // float4 index
    if (idx >= NN*HD/4) return;
    int c4 = idx & 63;
    float4 v = ((const float4*)g_r)[idx];
    float4 A = ((const float4*)g_A)[c4];
    float4 C = ((const float4*)g_C)[c4];
    float4 o = make_float4(v.x*A.x+C.x, v.y*A.y+C.y, v.z*A.z+C.z, v.w*A.w+C.w);
    if (residual) {
        float4 p = ((const float4*)g_xp)[idx];
        o.x += p.x; o.y += p.y; o.z += p.z; o.w += p.w;
    }
    ((float4*)g_xp)[idx] = o;
}

// ---------------- attention score: s[i] = sum_j lrelu(S1[i,j])*Wa2[j] + ba2 ----------------
__global__ __launch_bounds__(128) void score_kernel(const float* __restrict__ Wa2,
                                                    const float* __restrict__ ba2) {
    __shared__ float red[4];
    int j = threadIdx.x;
    float w2 = Wa2[j];
    for (int r = 0; r < 8; r++) {
        int i = blockIdx.x*8 + r;
        float v = g_h[(size_t)i*128 + j];
        v = (v > 0.f) ? v : 0.01f*v;
        float p = v * w2;
        #pragma unroll
        for (int off = 16; off; off >>= 1) p += __shfl_xor_sync(0xffffffffu, p, off);
        if ((j & 31) == 0) red[j >> 5] = p;
        __syncthreads();
        if (j == 0) g_score[i] = red[0]+red[1]+red[2]+red[3] + ba2[0];
        __syncthreads();
    }
}

// ---------------- softmax over all N (online max+sum) ----------------
__global__ void smax_part() {
    __shared__ float sm[256], ss[256];
    int t = threadIdx.x;
    float m = -3.4e38f, s = 0.f;
    for (int i = blockIdx.x*256 + t; i < NN; i += SCAN_BLKS*256) {
        float v = g_score[i];
        float nm = fmaxf(m, v);
        float ns = expf(v - nm);
        if (s > 0.f) ns += s * expf(m - nm);
        s = ns; m = nm;
    }
    sm[t] = m; ss[t] = s; __syncthreads();
    for (int off = 128; off; off >>= 1) {
        if (t < off) {
            float m2 = sm[t+off], s2 = ss[t+off];
            float nm = fmaxf(sm[t], m2);
            float acc = 0.f;
            if (ss[t] > 0.f) acc += ss[t] * expf(sm[t] - nm);
            if (s2    > 0.f) acc += s2    * expf(m2    - nm);
            sm[t] = nm; ss[t] = acc;
        }
        __syncthreads();
    }
    if (t == 0) { g_pm[blockIdx.x] = sm[0]; g_ps[blockIdx.x] = ss[0]; }
}
__global__ void smax_final() {
    __shared__ float sm[256], ss[256];
    int t = threadIdx.x;
    sm[t] = (t < SCAN_BLKS) ? g_pm[t] : -3.4e38f;
    ss[t] = (t < SCAN_BLKS) ? g_ps[t] : 0.f;
    __syncthreads();
    for (int off = 128; off; off >>= 1) {
        if (t < off) {
            float m2 = sm[t+off], s2 = ss[t+off];
            float nm = fmaxf(sm[t], m2);
            float acc = 0.f;
            if (ss[t] > 0.f) acc += ss[t] * expf(sm[t] - nm);
            if (s2    > 0.f) acc += s2    * expf(m2    - nm);
            sm[t] = nm; ss[t] = acc;
        }
        __syncthreads();
    }
    if (t == 0) { g_soft[0] = sm[0]; g_soft[1] = 1.f / ss[0]; }
}

// w[i] = exp(s[i]-max)*inv_sum ; also count per group via smem histogram
__global__ void wcnt_kernel(const int* __restrict__ batch) {
    __shared__ int hist[NG];
    int t = threadIdx.x;
    if (t < NG) hist[t] = 0;
    __syncthreads();
    int i = blockIdx.x*256 + t;
    if (i < NN) {
        g_w[i] = expf(g_score[i] - g_soft[0]) * g_soft[1];
        atomicAdd(&hist[batch[i]], 1);
    }
    __syncthreads();
    if (t < NG && hist[t]) atomicAdd(&g_cntf[t], (float)hist[t]);
}

// pooled[g] += sum xp[i]*w[i]  (batch sorted -> register accumulate, flush on change)
__global__ __launch_bounds__(256) void pool_kernel(const int* __restrict__ batch) {
    int t = threadIdx.x;   // column
    int row0 = blockIdx.x * 128;
    if (row0 >= NN) return;
    float acc = 0.f;
    int cur = batch[row0];
    for (int r = 0; r < 128; r++) {
        int i = row0 + r;
        if (i >= NN) break;
        int g = batch[i];
        if (g != cur) {
            if (acc != 0.f) atomicAdd(&g_pooled[cur*HD + t], acc);
            acc = 0.f; cur = g;
        }
        acc = fmaf(g_xp[(size_t)i*HD + t], g_w[i], acc);
    }
    atomicAdd(&g_pooled[cur*HD + t], acc);
}

// out[g][o] = (pooled[g]/max(cnt,1)) @ Wo + bo
__global__ void final_kernel(const float* __restrict__ Wo, const float* __restrict__ bo,
                             float* __restrict__ out) {
    int t = threadIdx.x;
    if (t >= NG*2) return;
    int g = t >> 1, o = t & 1;
    float s = 0.f;
    for (int h = 0; h < HD; h++) s = fmaf(g_pooled[g*HD + h], Wo[h*2 + o], s);
    out[t] = s / fmaxf(g_cntf[g], 1.f) + bo[o];
}

// ---------------- launch ----------------
extern "C" void kernel_launch(void* const* d_in, const int* in_sizes, int n_in,
                              void* d_out, int out_size) {
    const float* x      = (const float*)d_in[0];
    const int*   ei     = (const int*)d_in[1];
    const int*   src    = ei;
    const int*   dst    = ei + NE;
    const int*   batch  = (const int*)d_in[2];
    const float* bing   = (const float*)d_in[3];
    const float* binb   = (const float*)d_in[4];
    const float* W[3]   = {(const float*)d_in[5],  (const float*)d_in[9],  (const float*)d_in[13]};
    const float* bL[3]  = {(const float*)d_in[6],  (const float*)d_in[10], (const float*)d_in[14]};
    const float* bng[3] = {(const float*)d_in[7],  (const float*)d_in[11], (const float*)d_in[15]};
    const float* bnb[3] = {(const float*)d_in[8],  (const float*)d_in[12], (const float*)d_in[16]};
    const float* Wa1    = (const float*)d_in[17];
    const float* ba1    = (const float*)d_in[18];
    const float* Wa2    = (const float*)d_in[19];
    const float* ba2    = (const float*)d_in[20];
    const float* Wo     = (const float*)d_in[21];
    const float* bo     = (const float*)d_in[22];
    float* out = (float*)d_out;

    void* p;
    cudaGetSymbolAddress(&p, g_h);   float* ph   = (float*)p;
    cudaGetSymbolAddress(&p, g_xp);  float* pxp  = (float*)p;
    cudaGetSymbolAddress(&p, g_W0f); float* pw0f = (float*)p;
    cudaGetSymbolAddress(&p, g_cb);  float* pcb  = (float*)p;

    zero_init<<<SCAN_BLKS,256>>>();
    colstats_x<<<512,256>>>(x);
    finalize_in<<<1,256>>>(bing, binb);
    foldW0<<<HD,HD>>>(W[0]);
    foldB0<<<1,HD>>>(W[0]);
    deg_kernel<<<1024,256>>>(dst);
    dinv_kernel<<<SCAN_BLKS,256>>>();
    scan1<<<SCAN_BLKS,256>>>();
    scan2<<<1,256>>>();
    scan3<<<SCAN_BLKS,256>>>();
    fill_kernel<<<1024,256>>>(src, dst);

    dim3 gemm_grid((NN+127)/128, 2);
    int bn_blocks = (NN*HD/4 + 255)/256;

    // layer 0 (input BN folded into W0f/cb)
    sgemm_kernel<<<gemm_grid,256>>>(x, pw0f, pcb, ph, NN, HD);
    agg_kernel<<<(NN+31)/32,128>>>(bL[0]);
    finalize_hidden<<<1,256>>>(bng[0], bnb[0]);
    bnnorm_kernel<<<bn_blocks,256>>>(0);

    // layers 1,2 with residual
    for (int l = 1; l < 3; l++) {
        sgemm_kernel<<<gemm_grid,256>>>(pxp, W[l], nullptr, ph, NN, HD);
        agg_kernel<<<(NN+31)/32,128>>>(bL[l]);
        finalize_hidden<<<1,256>>>(bng[l], bnb[l]);
        bnnorm_kernel<<<bn_blocks,256>>>(1);
    }

    // attention
    dim3 attn_grid((NN+127)/128, 1);
    sgemm_kernel<<<attn_grid,256>>>(pxp, Wa1, ba1, ph, NN, 128);
    score_kernel<<<NN/8,128>>>(Wa2, ba2);
    smax_part<<<SCAN_BLKS,256>>>();
    smax_final<<<1,256>>>();
    wcnt_kernel<<<SCAN_BLKS,256>>>(batch);
    pool_kernel<<<(NN+127)/128,256>>>(batch);
    final_kernel<<<1,128>>>(Wo, bo, out);
}

// round 2
// speedup vs baseline: 1.2822x; 1.2822x over previous
#include <cuda_runtime.h>
#include <math.h>

#define NN 50000
#define NE 800000
#define HD 256
#define NG 64
#define SCAN_BLKS 196   // ceil(50000/256)

// ---------------- scratch (device globals; no runtime allocation) ----------------
__device__ __align__(16) float g_h [(size_t)NN*HD];   // GEMM output (also S1 [N,128] for attention)
__device__ __align__(16) float g_r [(size_t)NN*HD];   // post agg+relu
__device__ __align__(16) float g_xp[(size_t)NN*HD];   // layer activations
__device__ float g_dinv[NN];
__device__ int   g_cnt[NN];
__device__ int   g_incl[NN];
__device__ int   g_rowptr[NN+1];
__device__ int   g_cursor[NN];
__device__ int   g_col[NE];
__device__ int   g_bsum[SCAN_BLKS];
__device__ int   g_bscan[SCAN_BLKS];
__device__ __align__(16) float g_stat0[HD];
__device__ __align__(16) float g_stat1[HD];
__device__ __align__(16) float g_ain[HD], g_cin[HD];
__device__ __align__(16) float g_A[HD], g_C[HD];
__device__ __align__(16) float g_W0f[HD*HD];
__device__ __align__(16) float g_cb[HD];
__device__ float g_score[NN], g_w[NN];
__device__ float g_pm[SCAN_BLKS], g_ps[SCAN_BLKS];
__device__ float g_soft[2];
__device__ __align__(16) float g_pooled[NG*HD];
__device__ float g_cntf[NG];

// ---------------- helpers ----------------
__device__ __forceinline__ unsigned f2tf32(float x) {
    unsigned r;
    asm("cvt.rna.tf32.f32 %0, %1;" : "=r"(r) : "f"(x));
    return r;
}

__device__ __forceinline__ void mma_tf32(float* c,
    unsigned a0, unsigned a1, unsigned a2, unsigned a3,
    unsigned b0, unsigned b1)
{
    asm volatile(
        "mma.sync.aligned.m16n8k8.row.col.f32.tf32.tf32.f32 "
        "{%0,%1,%2,%3},{%4,%5,%6,%7},{%8,%9},{%0,%1,%2,%3};\n"
        : "+f"(c[0]), "+f"(c[1]), "+f"(c[2]), "+f"(c[3])
        : "r"(a0), "r"(a1), "r"(a2), "r"(a3), "r"(b0), "r"(b1));
}

// ---------------- init / zero ----------------
__global__ void zero_init() {
    int i = blockIdx.x * 256 + threadIdx.x;
    if (i < NN) g_cnt[i] = 0;
    if (i < NG*HD) g_pooled[i] = 0.f;
    if (i < NG) g_cntf[i] = 0.f;
    if (i < HD) { g_stat0[i] = 0.f; g_stat1[i] = 0.f; }
}

// ---------------- input BN stats (column sums over x) ----------------
__global__ void colstats_x(const float* __restrict__ x) {
    int t = threadIdx.x;  // column 0..255
    float s = 0.f, q = 0.f;
    for (int r = blockIdx.x; r < NN; r += gridDim.x) {
        float v = x[(size_t)r*HD + t];
        s += v; q += v*v;
    }
    atomicAdd(&g_stat0[t], s);
    atomicAdd(&g_stat1[t], q);
}

__global__ void finalize_in(const float* __restrict__ g, const float* __restrict__ b) {
    int t = threadIdx.x;
    float m = g_stat0[t] * (1.f/NN);
    float v = g_stat1[t] * (1.f/NN) - m*m;
    float rs = rsqrtf(v + 1e-5f);
    g_ain[t] = rs * g[t];
    g_cin[t] = b[t] - m * rs * g[t];
    g_stat0[t] = 0.f; g_stat1[t] = 0.f;
}

// Fold input-BN affine into W0: W0f[k][j] = a[k]*W0[k][j]; cb[j] = sum_k c[k]*W0[k][j]
__global__ void foldW0(const float* __restrict__ W0) {
    int k = blockIdx.x, j = threadIdx.x;
    g_W0f[k*HD + j] = g_ain[k] * W0[k*HD + j];
}
__global__ void foldB0(const float* __restrict__ W0) {
    int j = threadIdx.x;
    float s = 0.f;
    for (int k = 0; k < HD; k++) s += g_cin[k] * W0[k*HD + j];
    g_cb[j] = s;
}

// ---------------- degree / CSR build ----------------
__global__ void deg_kernel(const int* __restrict__ dst) {
    for (int e = blockIdx.x*blockDim.x + threadIdx.x; e < NE; e += gridDim.x*blockDim.x)
        atomicAdd(&g_cnt[dst[e]], 1);
}
__global__ void dinv_kernel() {
    int i = blockIdx.x*256 + threadIdx.x;
    if (i < NN) g_dinv[i] = rsqrtf((float)g_cnt[i] + 1.f);
}
__global__ void scan1() {
    __shared__ int sm[256];
    int t = threadIdx.x;
    int i = blockIdx.x*256 + t;
    int v = (i < NN) ? g_cnt[i] : 0;
    sm[t] = v; __syncthreads();
    for (int off = 1; off < 256; off <<= 1) {
        int tv = (t >= off) ? sm[t-off] : 0;
        __syncthreads();
        sm[t] += tv;
        __syncthreads();
    }
    if (i < NN) g_incl[i] = sm[t];
    if (t == 255) g_bsum[blockIdx.x] = sm[255];
}
__global__ void scan2() {
    __shared__ int sm[256];
    int t = threadIdx.x;
    sm[t] = (t < SCAN_BLKS) ? g_bsum[t] : 0; __syncthreads();
    for (int off = 1; off < 256; off <<= 1) {
        int tv = (t >= off) ? sm[t-off] : 0;
        __syncthreads();
        sm[t] += tv;
        __syncthreads();
    }
    if (t < SCAN_BLKS) g_bscan[t] = sm[t];
}
__global__ void scan3() {
    int t = threadIdx.x;
    int i = blockIdx.x*256 + t;
    if (i < NN) {
        int off = (blockIdx.x > 0) ? g_bscan[blockIdx.x-1] : 0;
        int ex = off + g_incl[i] - g_cnt[i];
        g_rowptr[i] = ex;
        g_cursor[i] = ex;
    }
    if (i == 0) g_rowptr[NN] = NE;
}
__global__ void fill_kernel(const int* __restrict__ src, const int* __restrict__ dst) {
    for (int e = blockIdx.x*blockDim.x + threadIdx.x; e < NE; e += gridDim.x*blockDim.x) {
        int d = dst[e];
        int p = atomicAdd(&g_cursor[d], 1);
        g_col[p] = src[e];
    }
}

// ---------------- 3xTF32 tensor-core GEMM: C[M,Nn] = A[M,256] @ B[256,Nn] (+bias) ----------------
// BM=128, BN=128, BK=16, 256 threads = 8 warps (2x4), warp tile 64x32.
__global__ __launch_bounds__(256) void tf32_gemm(
    const float* __restrict__ A, const float* __restrict__ B,
    const float* __restrict__ bias, float* __restrict__ C, int M, int Nn)
{
    __shared__ unsigned sAh[16][136], sAl[16][136];
    __shared__ unsigned sBh[16][136], sBl[16][136];
    int tid = threadIdx.x;
    int bm = blockIdx.x*128, bn = blockIdx.y*128;
    int lane = tid & 31, w = tid >> 5;
    int wm = (w >> 2) * 64, wn = (w & 3) * 32;
    int lrow = lane >> 2, lk = lane & 3;

    int aid  = tid * 2;
    int arow = aid >> 2;     // 0..127
    int ac4  = aid & 3;      // 0 or 2 (covers ac4, ac4+1)
    int bk   = aid >> 5;     // 0..15
    int bn4  = aid & 31;     // even (covers bn4, bn4+1)

    float4 ra[2], rb[2];
    float acc[4][4][4];
    #pragma unroll
    for (int a = 0; a < 4; a++)
        #pragma unroll
        for (int b = 0; b < 4; b++)
            #pragma unroll
            for (int cc = 0; cc < 4; cc++) acc[a][b][cc] = 0.f;

    // preload kt=0
    {
        const float* ap = A + (size_t)(bm+arow)*256 + ac4*4;
        if (bm + arow < M) { ra[0] = *(const float4*)ap; ra[1] = *(const float4*)(ap+4); }
        else { ra[0] = make_float4(0,0,0,0); ra[1] = ra[0]; }
        const float* bp = B + (size_t)bk*Nn + bn + bn4*4;
        rb[0] = *(const float4*)bp; rb[1] = *(const float4*)(bp+4);
    }

    for (int kt = 0; kt < 16; kt++) {
        // store staging -> smem (convert fp32 -> tf32 hi/lo)
        #pragma unroll
        for (int i = 0; i < 2; i++) {
            float v[4] = {ra[i].x, ra[i].y, ra[i].z, ra[i].w};
            #pragma unroll
            for (int j = 0; j < 4; j++) {
                unsigned h = f2tf32(v[j]);
                sAh[(ac4+i)*4 + j][arow] = h;
                sAl[(ac4+i)*4 + j][arow] = f2tf32(v[j] - __uint_as_float(h));
            }
        }
        #pragma unroll
        for (int i = 0; i < 2; i++) {
            float v[4] = {rb[i].x, rb[i].y, rb[i].z, rb[i].w};
            unsigned h[4], l[4];
            #pragma unroll
            for (int j = 0; j < 4; j++) {
                h[j] = f2tf32(v[j]);
                l[j] = f2tf32(v[j] - __uint_as_float(h[j]));
            }
            *(uint4*)&sBh[bk][(bn4+i)*4] = make_uint4(h[0],h[1],h[2],h[3]);
            *(uint4*)&sBl[bk][(bn4+i)*4] = make_uint4(l[0],l[1],l[2],l[3]);
        }
        __syncthreads();

        // prefetch next tile into regs (overlaps with compute)
        if (kt < 15) {
            int k0 = (kt+1)*16;
            const float* ap = A + (size_t)(bm+arow)*256 + k0 + ac4*4;
            if (bm + arow < M) { ra[0] = *(const float4*)ap; ra[1] = *(const float4*)(ap+4); }
            else { ra[0] = make_float4(0,0,0,0); ra[1] = ra[0]; }
            const float* bp = B + (size_t)(k0+bk)*Nn + bn + bn4*4;
            rb[0] = *(const float4*)bp; rb[1] = *(const float4*)(bp+4);
        }

        #pragma unroll
        for (int ks = 0; ks < 2; ks++) {
            int kb = ks*8 + lk;
            unsigned ah[4][4], al[4][4];
            #pragma unroll
            for (int mt = 0; mt < 4; mt++) {
                int m0 = wm + mt*16 + lrow;
                ah[mt][0] = sAh[kb][m0];   ah[mt][1] = sAh[kb][m0+8];
                ah[mt][2] = sAh[kb+4][m0]; ah[mt][3] = sAh[kb+4][m0+8];
                al[mt][0] = sAl[kb][m0];   al[mt][1] = sAl[kb][m0+8];
                al[mt][2] = sAl[kb+4][m0]; al[mt][3] = sAl[kb+4][m0+8];
            }
            #pragma unroll
            for (int nt = 0; nt < 4; nt++) {
                int n0 = wn + nt*8 + lrow;
                unsigned bh0 = sBh[kb][n0], bh1 = sBh[kb+4][n0];
                unsigned bl0 = sBl[kb][n0], bl1 = sBl[kb+4][n0];
                #pragma unroll
                for (int mt = 0; mt < 4; mt++) {
                    mma_tf32(acc[mt][nt], ah[mt][0],ah[mt][1],ah[mt][2],ah[mt][3], bh0, bh1);
                    mma_tf32(acc[mt][nt], al[mt][0],al[mt][1],al[mt][2],al[mt][3], bh0, bh1);
                    mma_tf32(acc[mt][nt], ah[mt][0],ah[mt][1],ah[mt][2],ah[mt][3], bl0, bl1);
                }
            }
        }
        __syncthreads();
    }

    // epilogue: bias add + store
    #pragma unroll
    for (int nt = 0; nt < 4; nt++) {
        int cidx = bn + wn + nt*8 + 2*lk;
        float b0v = bias ? bias[cidx]   : 0.f;
        float b1v = bias ? bias[cidx+1] : 0.f;
        #pragma unroll
        for (int mt = 0; mt < 4; mt++) {
            int r0 = bm + wm + mt*16 + lrow;
            if (r0 < M)
                *(float2*)(C + (size_t)r0*Nn + cidx) =
                    make_float2(acc[mt][nt][0]+b0v, acc[mt][nt][1]+b1v);
            if (r0 + 8 < M)
                *(float2*)(C + (size_t)(r0+8)*Nn + cidx) =
                    make_float2(acc[mt][nt][2]+b0v, acc[mt][nt][3]+b1v);
        }
    }
}

// ---------------- aggregation + bias + relu + BN-stat partials ----------------
// out = relu( sum_nb h[src]*dinv[src]*dinv[dst] + h[dst]*dinv^2 + b )
// 256 threads = 1 column each; 32 rows per block; neighbor loop unrolled x4 for MLP.
__global__ __launch_bounds__(256) void agg_kernel(const float* __restrict__ bias) {
    int c = threadIdx.x;
    int row0 = blockIdx.x * 32;
    float bia = bias[c];
    float ssum = 0.f, ssq = 0.f;
    for (int r = 0; r < 32; r++) {
        int i = row0 + r;
        if (i >= NN) break;
        float di = g_dinv[i];
        float acc = g_h[(size_t)i*HD + c] * di * di;
        int p = g_rowptr[i], e = g_rowptr[i+1];
        for (; p + 4 <= e; p += 4) {
            int s0 = g_col[p],   s1 = g_col[p+1];
            int s2 = g_col[p+2], s3 = g_col[p+3];
            float f0 = di*g_dinv[s0], f1 = di*g_dinv[s1];
            float f2 = di*g_dinv[s2], f3 = di*g_dinv[s3];
            float v0 = g_h[(size_t)s0*HD + c];
            float v1 = g_h[(size_t)s1*HD + c];
            float v2 = g_h[(size_t)s2*HD + c];
            float v3 = g_h[(size_t)s3*HD + c];
            acc = fmaf(v0, f0, acc); acc = fmaf(v1, f1, acc);
            acc = fmaf(v2, f2, acc); acc = fmaf(v3, f3, acc);
        }
        for (; p < e; p++) {
            int s = g_col[p];
            acc = fmaf(g_h[(size_t)s*HD + c], di*g_dinv[s], acc);
        }
        float v = fmaxf(acc + bia, 0.f);
        g_r[(size_t)i*HD + c] = v;
        ssum += v; ssq += v*v;
    }
    atomicAdd(&g_stat0[c], ssum);
    atomicAdd(&g_stat1[c], ssq);
}

__global__ void finalize_hidden(const float* __restrict__ g, const float* __restrict__ b) {
    int t = threadIdx.x;
    float m = g_stat0[t] * (1.f/NN);
    float v = g_stat1[t] * (1.f/NN) - m*m;
    float rs = rsqrtf(v + 1e-5f);
    g_A[t] = rs * g[t];
    g_C[t] = b[t] - m * rs * g[t];
    g_stat0[t] = 0.f; g_stat1[t] = 0.f;
}

// xp = r*A + C (+ xp if residual)
__global__ void bnnorm_kernel(int residual) {
    int idx = blockIdx.x*256 + threadIdx.x;       // float4 index
    if (idx >= NN*HD/4) return;
    int c4 = idx & 63;
    float4 v = ((const float4*)g_r)[idx];
    float4 A = ((const float4*)g_A)[c4];
    float4 C = ((const float4*)g_C)[c4];
    float4 o = make_float4(v.x*A.x+C.x, v.y*A.y+C.y, v.z*A.z+C.z, v.w*A.w+C.w);
    if (residual) {
        float4 p = ((const float4*)g_xp)[idx];
        o.x += p.x; o.y += p.y; o.z += p.z; o.w += p.w;
    }
    ((float4*)g_xp)[idx] = o;
}

// ---------------- attention score: s[i] = sum_j lrelu(S1[i,j])*Wa2[j] + ba2 ----------------
__global__ __launch_bounds__(128) void score_kernel(const float* __restrict__ Wa2,
                                                    const float* __restrict__ ba2) {
    __shared__ float red[4];
    int j = threadIdx.x;
    float w2 = Wa2[j];
    for (int r = 0; r < 8; r++) {
        int i = blockIdx.x*8 + r;
        float v = g_h[(size_t)i*128 + j];
        v = (v > 0.f) ? v : 0.01f*v;
        float p = v * w2;
        #pragma unroll
        for (int off = 16; off; off >>= 1) p += __shfl_xor_sync(0xffffffffu, p, off);
        if ((j & 31) == 0) red[j >> 5] = p;
        __syncthreads();
        if (j == 0) g_score[i] = red[0]+red[1]+red[2]+red[3] + ba2[0];
        __syncthreads();
    }
}

// ---------------- softmax over all N (online max+sum) ----------------
__global__ void smax_part() {
    __shared__ float sm[256], ss[256];
    int t = threadIdx.x;
    float m = -3.4e38f, s = 0.f;
    for (int i = blockIdx.x*256 + t; i < NN; i += SCAN_BLKS*256) {
        float v = g_score[i];
        float nm = fmaxf(m, v);
        float ns = expf(v - nm);
        if (s > 0.f) ns += s * expf(m - nm);
        s = ns; m = nm;
    }
    sm[t] = m; ss[t] = s; __syncthreads();
    for (int off = 128; off; off >>= 1) {
        if (t < off) {
            float m2 = sm[t+off], s2 = ss[t+off];
            float nm = fmaxf(sm[t], m2);
            float acc = 0.f;
            if (ss[t] > 0.f) acc += ss[t] * expf(sm[t] - nm);
            if (s2    > 0.f) acc += s2    * expf(m2    - nm);
            sm[t] = nm; ss[t] = acc;
        }
        __syncthreads();
    }
    if (t == 0) { g_pm[blockIdx.x] = sm[0]; g_ps[blockIdx.x] = ss[0]; }
}
__global__ void smax_final() {
    __shared__ float sm[256], ss[256];
    int t = threadIdx.x;
    sm[t] = (t < SCAN_BLKS) ? g_pm[t] : -3.4e38f;
    ss[t] = (t < SCAN_BLKS) ? g_ps[t] : 0.f;
    __syncthreads();
    for (int off = 128; off; off >>= 1) {
        if (t < off) {
            float m2 = sm[t+off], s2 = ss[t+off];
            float nm = fmaxf(sm[t], m2);
            float acc = 0.f;
            if (ss[t] > 0.f) acc += ss[t] * expf(sm[t] - nm);
            if (s2    > 0.f) acc += s2    * expf(m2    - nm);
            sm[t] = nm; ss[t] = acc;
        }
        __syncthreads();
    }
    if (t == 0) { g_soft[0] = sm[0]; g_soft[1] = 1.f / ss[0]; }
}

// w[i] = exp(s[i]-max)*inv_sum ; also count per group via smem histogram
__global__ void wcnt_kernel(const int* __restrict__ batch) {
    __shared__ int hist[NG];
    int t = threadIdx.x;
    if (t < NG) hist[t] = 0;
    __syncthreads();
    int i = blockIdx.x*256 + t;
    if (i < NN) {
        g_w[i] = expf(g_score[i] - g_soft[0]) * g_soft[1];
        atomicAdd(&hist[batch[i]], 1);
    }
    __syncthreads();
    if (t < NG && hist[t]) atomicAdd(&g_cntf[t], (float)hist[t]);
}

// pooled[g] += sum xp[i]*w[i]  (batch sorted -> register accumulate, flush on change)
__global__ __launch_bounds__(256) void pool_kernel(const int* __restrict__ batch) {
    int t = threadIdx.x;   // column
    int row0 = blockIdx.x * 128;
    if (row0 >= NN) return;
    float acc = 0.f;
    int cur = batch[row0];
    for (int r = 0; r < 128; r++) {
        int i = row0 + r;
        if (i >= NN) break;
        int g = batch[i];
        if (g != cur) {
            if (acc != 0.f) atomicAdd(&g_pooled[cur*HD + t], acc);
            acc = 0.f; cur = g;
        }
        acc = fmaf(g_xp[(size_t)i*HD + t], g_w[i], acc);
    }
    atomicAdd(&g_pooled[cur*HD + t], acc);
}

// out[g][o] = (pooled[g]/max(cnt,1)) @ Wo + bo
__global__ void final_kernel(const float* __restrict__ Wo, const float* __restrict__ bo,
                             float* __restrict__ out) {
    int t = threadIdx.x;
    if (t >= NG*2) return;
    int g = t >> 1, o = t & 1;
    float s = 0.f;
    for (int h = 0; h < HD; h++) s = fmaf(g_pooled[g*HD + h], Wo[h*2 + o], s);
    out[t] = s / fmaxf(g_cntf[g], 1.f) + bo[o];
}

// ---------------- launch ----------------
extern "C" void kernel_launch(void* const* d_in, const int* in_sizes, int n_in,
                              void* d_out, int out_size) {
    const float* x      = (const float*)d_in[0];
    const int*   ei     = (const int*)d_in[1];
    const int*   src    = ei;
    const int*   dst    = ei + NE;
    const int*   batch  = (const int*)d_in[2];
    const float* bing   = (const float*)d_in[3];
    const float* binb   = (const float*)d_in[4];
    const float* W[3]   = {(const float*)d_in[5],  (const float*)d_in[9],  (const float*)d_in[13]};
    const float* bL[3]  = {(const float*)d_in[6],  (const float*)d_in[10], (const float*)d_in[14]};
    const float* bng[3] = {(const float*)d_in[7],  (const float*)d_in[11], (const float*)d_in[15]};
    const float* bnb[3] = {(const float*)d_in[8],  (const float*)d_in[12], (const float*)d_in[16]};
    const float* Wa1    = (const float*)d_in[17];
    const float* ba1    = (const float*)d_in[18];
    const float* Wa2    = (const float*)d_in[19];
    const float* ba2    = (const float*)d_in[20];
    const float* Wo     = (const float*)d_in[21];
    const float* bo     = (const float*)d_in[22];
    float* out = (float*)d_out;

    void* p;
    cudaGetSymbolAddress(&p, g_h);   float* ph   = (float*)p;
    cudaGetSymbolAddress(&p, g_xp);  float* pxp  = (float*)p;
    cudaGetSymbolAddress(&p, g_W0f); float* pw0f = (float*)p;
    cudaGetSymbolAddress(&p, g_cb);  float* pcb  = (float*)p;

    zero_init<<<SCAN_BLKS,256>>>();
    colstats_x<<<512,256>>>(x);
    finalize_in<<<1,256>>>(bing, binb);
    foldW0<<<HD,HD>>>(W[0]);
    foldB0<<<1,HD>>>(W[0]);
    deg_kernel<<<1024,256>>>(dst);
    dinv_kernel<<<SCAN_BLKS,256>>>();
    scan1<<<SCAN_BLKS,256>>>();
    scan2<<<1,256>>>();
    scan3<<<SCAN_BLKS,256>>>();
    fill_kernel<<<1024,256>>>(src, dst);

    dim3 gemm_grid((NN+127)/128, 2);
    int agg_blocks = (NN+31)/32;
    int bn_blocks = (NN*HD/4 + 255)/256;

    // layer 0 (input BN folded into W0f/cb)
    tf32_gemm<<<gemm_grid,256>>>(x, pw0f, pcb, ph, NN, HD);
    agg_kernel<<<agg_blocks,256>>>(bL[0]);
    finalize_hidden<<<1,256>>>(bng[0], bnb[0]);
    bnnorm_kernel<<<bn_blocks,256>>>(0);

    // layers 1,2 with residual
    for (int l = 1; l < 3; l++) {
        tf32_gemm<<<gemm_grid,256>>>(pxp, W[l], nullptr, ph, NN, HD);
        agg_kernel<<<agg_blocks,256>>>(bL[l]);
        finalize_hidden<<<1,256>>>(bng[l], bnb[l]);
        bnnorm_kernel<<<bn_blocks,256>>>(1);
    }

    // attention
    dim3 attn_grid((NN+127)/128, 1);
    tf32_gemm<<<attn_grid,256>>>(pxp, Wa1, ba1, ph, NN, 128);
    score_kernel<<<NN/8,128>>>(Wa2, ba2);
    smax_part<<<SCAN_BLKS,256>>>();
    smax_final<<<1,256>>>();
    wcnt_kernel<<<SCAN_BLKS,256>>>(batch);
    pool_kernel<<<(NN+127)/128,256>>>(batch);
    final_kernel<<<1,128>>>(Wo, bo, out);
}

// round 4
// speedup vs baseline: 1.2967x; 1.0113x over previous
#include <cuda_runtime.h>
#include <math.h>

#define NN 50000
#define NE 800000
#define HD 256
#define NG 64
#define SCAN_BLKS 196   // ceil(50000/256)

// ---------------- scratch (device globals; no runtime allocation) ----------------
__device__ __align__(16) float g_h [(size_t)NN*HD];   // GEMM output (also S1 [N,128] for attention)
__device__ __align__(16) float g_r [(size_t)NN*HD];   // post agg+relu
__device__ __align__(16) float g_xp[(size_t)NN*HD];   // layer activations
__device__ float g_dinv[NN];
__device__ int   g_cnt[NN];
__device__ int   g_incl[NN];
__device__ int   g_rowptr[NN+1];
__device__ int   g_cursor[NN];
__device__ __align__(16) int2 g_edge[NE];             // {src, coef bits}
__device__ int   g_bsum[SCAN_BLKS];
__device__ int   g_bscan[SCAN_BLKS];
__device__ __align__(16) float g_stat0[HD];
__device__ __align__(16) float g_stat1[HD];
__device__ __align__(16) float g_ain[HD], g_cin[HD];
__device__ __align__(16) float g_A[HD], g_C[HD];
// pre-split tf32 weights: hi and lo parts
__device__ __align__(16) unsigned g_W0h[HD*HD], g_W0l[HD*HD];
__device__ __align__(16) unsigned g_W1h[HD*HD], g_W1l[HD*HD];
__device__ __align__(16) unsigned g_W2h[HD*HD], g_W2l[HD*HD];
__device__ __align__(16) unsigned g_Wa1h[HD*128], g_Wa1l[HD*128];
__device__ __align__(16) float g_cb[HD];
__device__ float g_score[NN], g_w[NN];
__device__ float g_pm[SCAN_BLKS], g_ps[SCAN_BLKS];
__device__ float g_soft[2];
__device__ __align__(16) float g_pooled[NG*HD];
__device__ float g_cntf[NG];

// ---------------- helpers ----------------
__device__ __forceinline__ unsigned f2tf32(float x) {
    unsigned r;
    asm("cvt.rna.tf32.f32 %0, %1;" : "=r"(r) : "f"(x));
    return r;
}

__device__ __forceinline__ void mma_tf32(float* c,
    unsigned a0, unsigned a1, unsigned a2, unsigned a3,
    unsigned b0, unsigned b1)
{
    asm volatile(
        "mma.sync.aligned.m16n8k8.row.col.f32.tf32.tf32.f32 "
        "{%0,%1,%2,%3},{%4,%5,%6,%7},{%8,%9},{%0,%1,%2,%3};\n"
        : "+f"(c[0]), "+f"(c[1]), "+f"(c[2]), "+f"(c[3])
        : "r"(a0), "r"(a1), "r"(a2), "r"(a3), "r"(b0), "r"(b1));
}

// ---------------- input BN stats (column sums over x) ----------------
__global__ void colstats_x(const float* __restrict__ x) {
    int t = threadIdx.x;  // column 0..255
    float s = 0.f, q = 0.f;
    for (int r = blockIdx.x; r < NN; r += gridDim.x) {
        float v = x[(size_t)r*HD + t];
        s += v; q += v*v;
    }
    atomicAdd(&g_stat0[t], s);
    atomicAdd(&g_stat1[t], q);
}

__global__ void finalize_in(const float* __restrict__ g, const float* __restrict__ b) {
    int t = threadIdx.x;
    float m = g_stat0[t] * (1.f/NN);
    float v = g_stat1[t] * (1.f/NN) - m*m;
    float rs = rsqrtf(v + 1e-5f);
    g_ain[t] = rs * g[t];
    g_cin[t] = b[t] - m * rs * g[t];
    g_stat0[t] = 0.f; g_stat1[t] = 0.f;
}

// Fold input BN into W0 (tf32 hi+lo) + folded bias cb
__global__ void fold0(const float* __restrict__ W0) {
    int j = threadIdx.x;
    int k = blockIdx.x;
    if (k < HD) {
        float v = g_ain[k] * W0[k*HD + j];
        unsigned h = f2tf32(v);
        g_W0h[k*HD + j] = h;
        g_W0l[k*HD + j] = f2tf32(v - __uint_as_float(h));
    } else {
        float s = 0.f;
        for (int kk = 0; kk < HD; kk++) s += g_cin[kk] * W0[kk*HD + j];
        g_cb[j] = s;
    }
}

// generic fp32 -> tf32 hi/lo pre-split
__global__ void presplit(const float* __restrict__ src, unsigned* __restrict__ dsth,
                         unsigned* __restrict__ dstl, int n) {
    int i = blockIdx.x*256 + threadIdx.x;
    if (i < n) {
        float v = src[i];
        unsigned h = f2tf32(v);
        dsth[i] = h;
        dstl[i] = f2tf32(v - __uint_as_float(h));
    }
}

// ---------------- degree / CSR build ----------------
__global__ void deg_kernel(const int* __restrict__ dst) {
    for (int e = blockIdx.x*blockDim.x + threadIdx.x; e < NE; e += gridDim.x*blockDim.x)
        atomicAdd(&g_cnt[dst[e]], 1);
}
__global__ void scan1() {   // also computes dinv
    __shared__ int sm[256];
    int t = threadIdx.x;
    int i = blockIdx.x*256 + t;
    int v = (i < NN) ? g_cnt[i] : 0;
    if (i < NN) g_dinv[i] = rsqrtf((float)v + 1.f);
    sm[t] = v; __syncthreads();
    for (int off = 1; off < 256; off <<= 1) {
        int tv = (t >= off) ? sm[t-off] : 0;
        __syncthreads();
        sm[t] += tv;
        __syncthreads();
    }
    if (i < NN) g_incl[i] = sm[t];
    if (t == 255) g_bsum[blockIdx.x] = sm[255];
}
__global__ void scan2() {
    __shared__ int sm[256];
    int t = threadIdx.x;
    sm[t] = (t < SCAN_BLKS) ? g_bsum[t] : 0; __syncthreads();
    for (int off = 1; off < 256; off <<= 1) {
        int tv = (t >= off) ? sm[t-off] : 0;
        __syncthreads();
        sm[t] += tv;
        __syncthreads();
    }
    if (t < SCAN_BLKS) g_bscan[t] = sm[t];
}
__global__ void scan3() {   // also resets g_cnt for next graph replay
    int t = threadIdx.x;
    int i = blockIdx.x*256 + t;
    if (i < NN) {
        int off = (blockIdx.x > 0) ? g_bscan[blockIdx.x-1] : 0;
        int ex = off + g_incl[i] - g_cnt[i];
        g_rowptr[i] = ex;
        g_cursor[i] = ex;
        g_cnt[i] = 0;
    }
    if (i == 0) g_rowptr[NN] = NE;
}
__global__ void fill_kernel(const int* __restrict__ src, const int* __restrict__ dst) {
    for (int e = blockIdx.x*blockDim.x + threadIdx.x; e < NE; e += gridDim.x*blockDim.x) {
        int d = dst[e];
        int s = src[e];
        int p = atomicAdd(&g_cursor[d], 1);
        float cf = g_dinv[s] * g_dinv[d];
        g_edge[p] = make_int2(s, __float_as_int(cf));
    }
}

// ---------------- 3xTF32 tensor-core GEMM: C[M,Nn] = A[M,256] @ B[256,Nn] (+bias) ----------------
// A converted inline (hi+lo), B pre-split tf32 hi+lo. BM=128, BN=128, BK=16, 8 warps, 64x32 warp tile.
__global__ __launch_bounds__(256) void tf32_gemm(
    const float* __restrict__ A, const unsigned* __restrict__ Bh,
    const unsigned* __restrict__ Bl,
    const float* __restrict__ bias, float* __restrict__ C, int M, int Nn)
{
    __shared__ unsigned sAh[16][136], sAl[16][136];
    __shared__ unsigned sBh[16][136], sBl[16][136];
    int tid = threadIdx.x;
    int bm = blockIdx.x*128, bn = blockIdx.y*128;
    int lane = tid & 31, w = tid >> 5;
    int wm = (w >> 2) * 64, wn = (w & 3) * 32;
    int lrow = lane >> 2, lk = lane & 3;

    int aid  = tid * 2;
    int arow = aid >> 2;     // 0..127
    int ac4  = aid & 3;      // 0 or 2
    int bk   = aid >> 5;     // 0..15
    int bn4  = aid & 31;     // even

    float4 ra[2]; uint4 rbh[2], rbl[2];
    float acc[4][4][4];
    #pragma unroll
    for (int a = 0; a < 4; a++)
        #pragma unroll
        for (int b = 0; b < 4; b++)
            #pragma unroll
            for (int cc = 0; cc < 4; cc++) acc[a][b][cc] = 0.f;

    // preload kt=0
    {
        const float* ap = A + (size_t)(bm+arow)*256 + ac4*4;
        if (bm + arow < M) { ra[0] = *(const float4*)ap; ra[1] = *(const float4*)(ap+4); }
        else { ra[0] = make_float4(0,0,0,0); ra[1] = ra[0]; }
        size_t bo = (size_t)bk*Nn + bn + bn4*4;
        rbh[0] = *(const uint4*)(Bh+bo); rbh[1] = *(const uint4*)(Bh+bo+4);
        rbl[0] = *(const uint4*)(Bl+bo); rbl[1] = *(const uint4*)(Bl+bo+4);
    }

    for (int kt = 0; kt < 16; kt++) {
        #pragma unroll
        for (int i = 0; i < 2; i++) {
            float v[4] = {ra[i].x, ra[i].y, ra[i].z, ra[i].w};
            #pragma unroll
            for (int j = 0; j < 4; j++) {
                unsigned h = f2tf32(v[j]);
                sAh[(ac4+i)*4 + j][arow] = h;
                sAl[(ac4+i)*4 + j][arow] = f2tf32(v[j] - __uint_as_float(h));
            }
        }
        *(uint4*)&sBh[bk][bn4*4]     = rbh[0];
        *(uint4*)&sBh[bk][(bn4+1)*4] = rbh[1];
        *(uint4*)&sBl[bk][bn4*4]     = rbl[0];
        *(uint4*)&sBl[bk][(bn4+1)*4] = rbl[1];
        __syncthreads();

        if (kt < 15) {
            int k0 = (kt+1)*16;
            const float* ap = A + (size_t)(bm+arow)*256 + k0 + ac4*4;
            if (bm + arow < M) { ra[0] = *(const float4*)ap; ra[1] = *(const float4*)(ap+4); }
            else { ra[0] = make_float4(0,0,0,0); ra[1] = ra[0]; }
            size_t bo = (size_t)(k0+bk)*Nn + bn + bn4*4;
            rbh[0] = *(const uint4*)(Bh+bo); rbh[1] = *(const uint4*)(Bh+bo+4);
            rbl[0] = *(const uint4*)(Bl+bo); rbl[1] = *(const uint4*)(Bl+bo+4);
        }

        #pragma unroll
        for (int ks = 0; ks < 2; ks++) {
            int kb = ks*8 + lk;
            unsigned ah[4][4], al[4][4];
            #pragma unroll
            for (int mt = 0; mt < 4; mt++) {
                int m0 = wm + mt*16 + lrow;
                ah[mt][0] = sAh[kb][m0];   ah[mt][1] = sAh[kb][m0+8];
                ah[mt][2] = sAh[kb+4][m0]; ah[mt][3] = sAh[kb+4][m0+8];
                al[mt][0] = sAl[kb][m0];   al[mt][1] = sAl[kb][m0+8];
                al[mt][2] = sAl[kb+4][m0]; al[mt][3] = sAl[kb+4][m0+8];
            }
            #pragma unroll
            for (int nt = 0; nt < 4; nt++) {
                int n0 = wn + nt*8 + lrow;
                unsigned bh0 = sBh[kb][n0], bh1 = sBh[kb+4][n0];
                unsigned bl0 = sBl[kb][n0], bl1 = sBl[kb+4][n0];
                #pragma unroll
                for (int mt = 0; mt < 4; mt++) {
                    mma_tf32(acc[mt][nt], ah[mt][0],ah[mt][1],ah[mt][2],ah[mt][3], bh0, bh1);
                    mma_tf32(acc[mt][nt], al[mt][0],al[mt][1],al[mt][2],al[mt][3], bh0, bh1);
                    mma_tf32(acc[mt][nt], ah[mt][0],ah[mt][1],ah[mt][2],ah[mt][3], bl0, bl1);
                }
            }
        }
        __syncthreads();
    }

    #pragma unroll
    for (int nt = 0; nt < 4; nt++) {
        int cidx = bn + wn + nt*8 + 2*lk;
        float b0v = bias ? bias[cidx]   : 0.f;
        float b1v = bias ? bias[cidx+1] : 0.f;
        #pragma unroll
        for (int mt = 0; mt < 4; mt++) {
            int r0 = bm + wm + mt*16 + lrow;
            if (r0 < M)
                *(float2*)(C + (size_t)r0*Nn + cidx) =
                    make_float2(acc[mt][nt][0]+b0v, acc[mt][nt][1]+b1v);
            if (r0 + 8 < M)
                *(float2*)(C + (size_t)(r0+8)*Nn + cidx) =
                    make_float2(acc[mt][nt][2]+b0v, acc[mt][nt][3]+b1v);
        }
    }
}

// ---------------- aggregation + bias + relu + BN-stat partials ----------------
__global__ __launch_bounds__(256) void agg_kernel(const float* __restrict__ bias) {
    int c = threadIdx.x;
    int row0 = blockIdx.x * 32;
    float bia = bias[c];
    float ssum = 0.f, ssq = 0.f;
    for (int r = 0; r < 32; r++) {
        int i = row0 + r;
        if (i >= NN) break;
        float di = g_dinv[i];
        float acc = g_h[(size_t)i*HD + c] * di * di;
        int p = g_rowptr[i], e = g_rowptr[i+1];
        for (; p + 8 <= e; p += 8) {
            int2 e0 = g_edge[p],   e1 = g_edge[p+1];
            int2 e2 = g_edge[p+2], e3 = g_edge[p+3];
            int2 e4 = g_edge[p+4], e5 = g_edge[p+5];
            int2 e6 = g_edge[p+6], e7 = g_edge[p+7];
            float v0 = g_h[(size_t)e0.x*HD + c];
            float v1 = g_h[(size_t)e1.x*HD + c];
            float v2 = g_h[(size_t)e2.x*HD + c];
            float v3 = g_h[(size_t)e3.x*HD + c];
            float v4 = g_h[(size_t)e4.x*HD + c];
            float v5 = g_h[(size_t)e5.x*HD + c];
            float v6 = g_h[(size_t)e6.x*HD + c];
            float v7 = g_h[(size_t)e7.x*HD + c];
            acc = fmaf(v0, __int_as_float(e0.y), acc);
            acc = fmaf(v1, __int_as_float(e1.y), acc);
            acc = fmaf(v2, __int_as_float(e2.y), acc);
            acc = fmaf(v3, __int_as_float(e3.y), acc);
            acc = fmaf(v4, __int_as_float(e4.y), acc);
            acc = fmaf(v5, __int_as_float(e5.y), acc);
            acc = fmaf(v6, __int_as_float(e6.y), acc);
            acc = fmaf(v7, __int_as_float(e7.y), acc);
        }
        for (; p < e; p++) {
            int2 ed = g_edge[p];
            acc = fmaf(g_h[(size_t)ed.x*HD + c], __int_as_float(ed.y), acc);
        }
        float v = fmaxf(acc + bia, 0.f);
        g_r[(size_t)i*HD + c] = v;
        ssum += v; ssq += v*v;
    }
    atomicAdd(&g_stat0[c], ssum);
    atomicAdd(&g_stat1[c], ssq);
}

__global__ void finalize_hidden(const float* __restrict__ g, const float* __restrict__ b) {
    int t = threadIdx.x;
    float m = g_stat0[t] * (1.f/NN);
    float v = g_stat1[t] * (1.f/NN) - m*m;
    float rs = rsqrtf(v + 1e-5f);
    g_A[t] = rs * g[t];
    g_C[t] = b[t] - m * rs * g[t];
    g_stat0[t] = 0.f; g_stat1[t] = 0.f;
}

// xp = r*A + C (+ xp if residual)
__global__ void bnnorm_kernel(int residual) {
    int idx = blockIdx.x*256 + threadIdx.x;       // float4 index
    if (idx >= NN*HD/4) return;
    int c4 = idx & 63;
    float4 v = ((const float4*)g_r)[idx];
    float4 A = ((const float4*)g_A)[c4];
    float4 C = ((const float4*)g_C)[c4];
    float4 o = make_float4(v.x*A.x+C.x, v.y*A.y+C.y, v.z*A.z+C.z, v.w*A.w+C.w);
    if (residual) {
        float4 p = ((const float4*)g_xp)[idx];
        o.x += p.x; o.y += p.y; o.z += p.z; o.w += p.w;
    }
    ((float4*)g_xp)[idx] = o;
}

// ---------------- attention score ----------------
__global__ __launch_bounds__(128) void score_kernel(const float* __restrict__ Wa2,
                                                    const float* __restrict__ ba2) {
    __shared__ float red[4];
    int j = threadIdx.x;
    float w2 = Wa2[j];
    for (int r = 0; r < 8; r++) {
        int i = blockIdx.x*8 + r;
        float v = g_h[(size_t)i*128 + j];
        v = (v > 0.f) ? v : 0.01f*v;
        float p = v * w2;
        #pragma unroll
        for (int off = 16; off; off >>= 1) p += __shfl_xor_sync(0xffffffffu, p, off);
        if ((j & 31) == 0) red[j >> 5] = p;
        __syncthreads();
        if (j == 0) g_score[i] = red[0]+red[1]+red[2]+red[3] + ba2[0];
        __syncthreads();
    }
}

// ---------------- softmax over all N ----------------
__global__ void smax_part() {
    __shared__ float sm[256], ss[256];
    int t = threadIdx.x;
    float m = -3.4e38f, s = 0.f;
    for (int i = blockIdx.x*256 + t; i < NN; i += SCAN_BLKS*256) {
        float v = g_score[i];
        float nm = fmaxf(m, v);
        float ns = expf(v - nm);
        if (s > 0.f) ns += s * expf(m - nm);
        s = ns; m = nm;
    }
    sm[t] = m; ss[t] = s; __syncthreads();
    for (int off = 128; off; off >>= 1) {
        if (t < off) {
            float m2 = sm[t+off], s2 = ss[t+off];
            float nm = fmaxf(sm[t], m2);
            float acc = 0.f;
            if (ss[t] > 0.f) acc += ss[t] * expf(sm[t] - nm);
            if (s2    > 0.f) acc += s2    * expf(m2    - nm);
            sm[t] = nm; ss[t] = acc;
        }
        __syncthreads();
    }
    if (t == 0) { g_pm[blockIdx.x] = sm[0]; g_ps[blockIdx.x] = ss[0]; }
}
__global__ void smax_final() {
    __shared__ float sm[256], ss[256];
    int t = threadIdx.x;
    sm[t] = (t < SCAN_BLKS) ? g_pm[t] : -3.4e38f;
    ss[t] = (t < SCAN_BLKS) ? g_ps[t] : 0.f;
    __syncthreads();
    for (int off = 128; off; off >>= 1) {
        if (t < off) {
            float m2 = sm[t+off], s2 = ss[t+off];
            float nm = fmaxf(sm[t], m2);
            float acc = 0.f;
            if (ss[t] > 0.f) acc += ss[t] * expf(sm[t] - nm);
            if (s2    > 0.f) acc += s2    * expf(m2    - nm);
            sm[t] = nm; ss[t] = acc;
        }
        __syncthreads();
    }
    if (t == 0) { g_soft[0] = sm[0]; g_soft[1] = 1.f / ss[0]; }
}

__global__ void wcnt_kernel(const int* __restrict__ batch) {
    __shared__ int hist[NG];
    int t = threadIdx.x;
    if (t < NG) hist[t] = 0;
    __syncthreads();
    int i = blockIdx.x*256 + t;
    if (i < NN) {
        g_w[i] = expf(g_score[i] - g_soft[0]) * g_soft[1];
        atomicAdd(&hist[batch[i]], 1);
    }
    __syncthreads();
    if (t < NG && hist[t]) atomicAdd(&g_cntf[t], (float)hist[t]);
}

__global__ __launch_bounds__(256) void pool_kernel(const int* __restrict__ batch) {
    int t = threadIdx.x;   // column
    int row0 = blockIdx.x * 128;
    if (row0 >= NN) return;
    float acc = 0.f;
    int cur = batch[row0];
    for (int r = 0; r < 128; r++) {
        int i = row0 + r;
        if (i >= NN) break;
        int g = batch[i];
        if (g != cur) {
            if (acc != 0.f) atomicAdd(&g_pooled[cur*HD + t], acc);
            acc = 0.f; cur = g;
        }
        acc = fmaf(g_xp[(size_t)i*HD + t], g_w[i], acc);
    }
    atomicAdd(&g_pooled[cur*HD + t], acc);
}

// out[g][o] = (pooled[g]/max(cnt,1)) @ Wo + bo  ; then reset pooled/cntf for next replay
__global__ void final_kernel(const float* __restrict__ Wo, const float* __restrict__ bo,
                             float* __restrict__ out) {
    int t = threadIdx.x;
    float s = 0.f;
    int g = t >> 1, o = t & 1;
    if (t < NG*2) {
        for (int h = 0; h < HD; h++) s = fmaf(g_pooled[g*HD + h], Wo[h*2 + o], s);
        s = s / fmaxf(g_cntf[g], 1.f) + bo[o];
    }
    __syncthreads();   // all reads of pooled/cntf done
    if (t < NG*2) out[t] = s;
    for (int i = t; i < NG*HD; i += 128) g_pooled[i] = 0.f;
    if (t < NG) g_cntf[t] = 0.f;
}

// ---------------- launch ----------------
extern "C" void kernel_launch(void* const* d_in, const int* in_sizes, int n_in,
                              void* d_out, int out_size) {
    const float* x      = (const float*)d_in[0];
    const int*   ei     = (const int*)d_in[1];
    const int*   src    = ei;
    const int*   dst    = ei + NE;
    const int*   batch  = (const int*)d_in[2];
    const float* bing   = (const float*)d_in[3];
    const float* binb   = (const float*)d_in[4];
    const float* W[3]   = {(const float*)d_in[5],  (const float*)d_in[9],  (const float*)d_in[13]};
    const float* bL[3]  = {(const float*)d_in[6],  (const float*)d_in[10], (const float*)d_in[14]};
    const float* bng[3] = {(const float*)d_in[7],  (const float*)d_in[11], (const float*)d_in[15]};
    const float* bnb[3] = {(const float*)d_in[8],  (const float*)d_in[12], (const float*)d_in[16]};
    const float* Wa1    = (const float*)d_in[17];
    const float* ba1    = (const float*)d_in[18];
    const float* Wa2    = (const float*)d_in[19];
    const float* ba2    = (const float*)d_in[20];
    const float* Wo     = (const float*)d_in[21];
    const float* bo     = (const float*)d_in[22];
    float* out = (float*)d_out;

    void* p;
    cudaGetSymbolAddress(&p, g_h);    float* ph   = (float*)p;
    cudaGetSymbolAddress(&p, g_xp);   float* pxp  = (float*)p;
    cudaGetSymbolAddress(&p, g_W0h);  unsigned* pw0h = (unsigned*)p;
    cudaGetSymbolAddress(&p, g_W0l);  unsigned* pw0l = (unsigned*)p;
    cudaGetSymbolAddress(&p, g_W1h);  unsigned* pw1h = (unsigned*)p;
    cudaGetSymbolAddress(&p, g_W1l);  unsigned* pw1l = (unsigned*)p;
    cudaGetSymbolAddress(&p, g_W2h);  unsigned* pw2h = (unsigned*)p;
    cudaGetSymbolAddress(&p, g_W2l);  unsigned* pw2l = (unsigned*)p;
    cudaGetSymbolAddress(&p, g_Wa1h); unsigned* pwah = (unsigned*)p;
    cudaGetSymbolAddress(&p, g_Wa1l); unsigned* pwal = (unsigned*)p;
    cudaGetSymbolAddress(&p, g_cb);   float* pcb  = (float*)p;

    dim3 gemm_grid((NN+127)/128, 2);
    int agg_blocks = (NN+31)/32;
    int bn_blocks = (NN*HD/4 + 255)/256;

    // launches ordered so the 4th is the layer-0 GEMM (ncu -s window)
    colstats_x<<<512,256>>>(x);
    finalize_in<<<1,256>>>(bing, binb);
    fold0<<<HD+1,HD>>>(W[0]);
    tf32_gemm<<<gemm_grid,256>>>(x, pw0h, pw0l, pcb, ph, NN, HD);   // <- profiled

    // CSR build (independent of GEMM result)
    deg_kernel<<<1024,256>>>(dst);
    scan1<<<SCAN_BLKS,256>>>();
    scan2<<<1,256>>>();
    scan3<<<SCAN_BLKS,256>>>();
    fill_kernel<<<1024,256>>>(src, dst);

    // pre-split remaining weights to tf32 hi/lo
    presplit<<<(HD*HD+255)/256,256>>>(W[1], pw1h, pw1l, HD*HD);
    presplit<<<(HD*HD+255)/256,256>>>(W[2], pw2h, pw2l, HD*HD);
    presplit<<<(HD*128+255)/256,256>>>(Wa1, pwah, pwal, HD*128);

    // layer 0
    agg_kernel<<<agg_blocks,256>>>(bL[0]);
    finalize_hidden<<<1,256>>>(bng[0], bnb[0]);
    bnnorm_kernel<<<bn_blocks,256>>>(0);

    // layers 1,2 with residual
    unsigned* pwsh[3] = {pw0h, pw1h, pw2h};
    unsigned* pwsl[3] = {pw0l, pw1l, pw2l};
    for (int l = 1; l < 3; l++) {
        tf32_gemm<<<gemm_grid,256>>>(pxp, pwsh[l], pwsl[l], nullptr, ph, NN, HD);
        agg_kernel<<<agg_blocks,256>>>(bL[l]);
        finalize_hidden<<<1,256>>>(bng[l], bnb[l]);
        bnnorm_kernel<<<bn_blocks,256>>>(1);
    }

    // attention
    dim3 attn_grid((NN+127)/128, 1);
    tf32_gemm<<<attn_grid,256>>>(pxp, pwah, pwal, ba1, ph, NN, 128);
    score_kernel<<<NN/8,128>>>(Wa2, ba2);
    smax_part<<<SCAN_BLKS,256>>>();
    smax_final<<<1,256>>>();
    wcnt_kernel<<<SCAN_BLKS,256>>>(batch);
    pool_kernel<<<(NN+127)/128,256>>>(batch);
    final_kernel<<<1,128>>>(Wo, bo, out);
}